// round 14
// baseline (speedup 1.0000x reference)
#include <cuda_runtime.h>
#include <cuda_fp16.h>
#include <mma.h>
#include <math.h>
#include <stdint.h>

using namespace nvcuda;

#define Bn 8
#define Ln 2048
#define Dn 512
#define Mn 8
#define KHn 256
#define BMn 64
#define Tn (Bn*Ln)

// ---------------- scratch ----------------
__device__ __half g_parth[(size_t)BMn*8*64*KHn]; // [bm*8+sp][d][k] fp16 split-K partials
__device__ float  g_mixpre[(size_t)Tn*Dn];
__device__ float  g_mix [(size_t)Tn*Dn];
__device__ float  g_pe  [(size_t)Ln*Dn];         // sinusoidal PE table
__device__ __half g_gluh[(size_t)Tn*Dn];
__device__ __half g_ln1h[(size_t)Tn*Dn];
__device__ __half g_acth[(size_t)Tn*Dn];
__device__ __half g_bwh [(size_t)1024*512];
__device__ __half g_lwh [(size_t)512*512];
__device__ __half g_xh  [(size_t)Tn*Dn];
__device__ __half g_w1f1h[(size_t)Mn*64*64];
__device__ __half g_w2f1h[(size_t)Mn*64*64];
__device__ __half g_w1f2h[(size_t)Mn*256*64];
__device__ __half g_w2f2h[(size_t)Mn*256*64];
__device__ __half g_hidh[(size_t)BMn*2*Ln*64];   // [(bm*2+net)][l][64]
__device__ __half g_W1h [(size_t)BMn*Ln*256];    // [bm][l][k]
__device__ __half g_W2h [(size_t)BMn*Ln*256];    // [bm][l][k]
__device__ __half g_out1h[(size_t)BMn*256*64];   // [bm][k][d]

__device__ __forceinline__ float gelu_f(float v){
  return 0.5f*v*(1.0f+erff(v*0.70710678118654752f));
}

// cp.async 16B helper
__device__ __forceinline__ void cpa16(void* dst, const void* src){
  uint32_t d;
  asm("{ .reg .u64 t; cvta.to.shared.u64 t, %1; cvt.u32.u64 %0, t; }" : "=r"(d) : "l"(dst));
  asm volatile("cp.async.ca.shared.global [%0], [%1], 16;" :: "r"(d), "l"(src));
}
#define CPA_COMMIT() asm volatile("cp.async.commit_group;")
#define CPA_WAIT1()  asm volatile("cp.async.wait_group 1;")
#define CPA_WAIT0()  asm volatile("cp.async.wait_group 0;")

// ---------------- K0: fused prep (PE table + all fp16 conversions) ----------------
__global__ void k_prep(const float* __restrict__ x,
    const float* __restrict__ w1f1w, const float* __restrict__ w2f1w,
    const float* __restrict__ w1f2w, const float* __restrict__ w2f2w,
    const float* __restrict__ bw, const float* __restrict__ lw){
  int i = blockIdx.x*256 + threadIdx.x;
  if (i < 1048576){
    int l = i>>9, ch = i&511;
    const float c0 = -9.210340371976184f / 512.0f;
    float ang = (float)l * expf((float)(ch & ~1) * c0);
    g_pe[i] = (ch & 1) ? cosf(ang) : sinf(ang);
    return;
  }
  i -= 1048576;
  if (i < 8388608){ g_xh[i] = __float2half_rn(x[i]); return; }
  i -= 8388608;
  if (i < 32768){ g_w1f1h[i] = __float2half_rn(w1f1w[i]); return; }
  i -= 32768;
  if (i < 32768){ g_w2f1h[i] = __float2half_rn(w2f1w[i]); return; }
  i -= 32768;
  if (i < 131072){ g_w1f2h[i] = __float2half_rn(w1f2w[i]); return; }
  i -= 131072;
  if (i < 131072){ g_w2f2h[i] = __float2half_rn(w2f2w[i]); return; }
  i -= 131072;
  if (i < 524288){ g_bwh[i] = __float2half_rn(bw[i]); return; }
  i -= 524288;
  g_lwh[i] = __float2half_rn(lw[i]);
}

// ---------------- K1a: hidden = gelu(fc1 @ (x+PE) + b), wmma ----------------
#define PA_SMEM (18432 + 67584)
__global__ void __launch_bounds__(256) k_pmlpA(
    const float* __restrict__ x,
    const float* __restrict__ b1f1, const float* __restrict__ b2f1){
  extern __shared__ char psm[];
  __half* Ah = (__half*)psm;             // 128 x 72
  __half* Bh = (__half*)(psm + 18432);   // 128 x 72
  float*  Cs = (float*)(psm + 18432);    // 128 x 132 (union with Bh)
  const int l0 = blockIdx.x*128;
  const int bm = blockIdx.y, b = bm>>3, m = bm&7;
  const int tid = threadIdx.x, wid = tid>>5;
  const int wm = wid&3, wn = wid>>2;

  #pragma unroll 4
  for (int i=0;i<32;i++){
    int idx=i*256+tid, tok=idx>>6, f=idx&63;
    int ch = m*64+f, l = l0+tok;
    Ah[tok*72+f] = __float2half_rn(x[(size_t)(b*Ln+l)*Dn+ch] + g_pe[(size_t)l*Dn+ch]);
  }
  #pragma unroll
  for (int i=0;i<4;i++){
    int idx=i*256+tid, n=idx>>3, u=idx&7;
    const __half* w = (n>=64)? g_w2f1h : g_w1f1h;
    *(uint4*)&Bh[n*72+u*8] = *(const uint4*)&w[m*4096 + (n&63)*64 + u*8];
  }
  __syncthreads();

  wmma::fragment<wmma::accumulator,16,16,16,float> cf[2][4];
  #pragma unroll
  for (int r=0;r<2;r++)
    #pragma unroll
    for (int c=0;c<4;c++) wmma::fill_fragment(cf[r][c], 0.0f);
  #pragma unroll
  for (int ks=0; ks<64; ks+=16){
    wmma::fragment<wmma::matrix_a,16,16,16,__half,wmma::row_major> af[2];
    wmma::fragment<wmma::matrix_b,16,16,16,__half,wmma::col_major> bf[4];
    #pragma unroll
    for (int r=0;r<2;r++)
      wmma::load_matrix_sync(af[r], &Ah[(wm*32+r*16)*72 + ks], 72);
    #pragma unroll
    for (int c=0;c<4;c++)
      wmma::load_matrix_sync(bf[c], &Bh[(wn*64+c*16)*72 + ks], 72);
    #pragma unroll
    for (int r=0;r<2;r++)
      #pragma unroll
      for (int c=0;c<4;c++)
        wmma::mma_sync(cf[r][c], af[r], bf[c], cf[r][c]);
  }
  __syncthreads();
  #pragma unroll
  for (int r=0;r<2;r++)
    #pragma unroll
    for (int c=0;c<4;c++)
      wmma::store_matrix_sync(&Cs[(wm*32+r*16)*132 + wn*64+c*16], cf[r][c], 132,
                              wmma::mem_row_major);
  __syncthreads();
  #pragma unroll 4
  for (int i=0;i<64;i++){
    int idx=i*256+tid, tok=idx>>7, n=idx&127;
    int net=n>>6, hid=n&63;
    float bias = net? b2f1[m*64+hid] : b1f1[m*64+hid];
    float v = gelu_f(Cs[tok*132+n] + bias);
    g_hidh[((size_t)(bm*2+net)*Ln + l0+tok)*64 + hid] = __float2half_rn(v);
  }
}

// ---------------- K1b: W = fc2 @ hidden + b, wmma ----------------
__global__ void __launch_bounds__(256) k_pmlpB(
    const float* __restrict__ b1f2, const float* __restrict__ b2f2){
  extern __shared__ char psm[];
  __half* Ah = (__half*)psm;             // 128 x 72
  __half* Bh = (__half*)(psm + 18432);   // 128 x 72
  float*  Cs = (float*)(psm + 18432);    // 128 x 132
  const int l0 = blockIdx.x*128;
  const int bmnet = blockIdx.y, bm = bmnet>>1, net = bmnet&1, m = bm&7;
  const int tid = threadIdx.x, wid = tid>>5;
  const int wm = wid&3, wn = wid>>2;
  const __half* w = net? g_w2f2h : g_w1f2h;
  const float* bias = net? b2f2 : b1f2;
  __half* dst = net? g_W2h : g_W1h;

  #pragma unroll
  for (int i=0;i<4;i++){
    int idx=i*256+tid, row=idx>>3, u=idx&7;
    *(uint4*)&Ah[row*72+u*8] =
      *(const uint4*)&g_hidh[((size_t)(bm*2+net)*Ln + l0+row)*64 + u*8];
  }
  for (int pass=0; pass<2; pass++){
    const int n0 = pass*128;
    #pragma unroll
    for (int i=0;i<4;i++){
      int idx=i*256+tid, n=idx>>3, u=idx&7;
      *(uint4*)&Bh[n*72+u*8] = *(const uint4*)&w[m*16384 + (size_t)(n0+n)*64 + u*8];
    }
    __syncthreads();
    wmma::fragment<wmma::accumulator,16,16,16,float> cf[2][4];
    #pragma unroll
    for (int r=0;r<2;r++)
      #pragma unroll
      for (int c=0;c<4;c++) wmma::fill_fragment(cf[r][c], 0.0f);
    #pragma unroll
    for (int ks=0; ks<64; ks+=16){
      wmma::fragment<wmma::matrix_a,16,16,16,__half,wmma::row_major> af[2];
      wmma::fragment<wmma::matrix_b,16,16,16,__half,wmma::col_major> bf[4];
      #pragma unroll
      for (int r=0;r<2;r++)
        wmma::load_matrix_sync(af[r], &Ah[(wm*32+r*16)*72 + ks], 72);
      #pragma unroll
      for (int c=0;c<4;c++)
        wmma::load_matrix_sync(bf[c], &Bh[(wn*64+c*16)*72 + ks], 72);
      #pragma unroll
      for (int r=0;r<2;r++)
        #pragma unroll
        for (int c=0;c<4;c++)
          wmma::mma_sync(cf[r][c], af[r], bf[c], cf[r][c]);
    }
    __syncthreads();
    #pragma unroll
    for (int r=0;r<2;r++)
      #pragma unroll
      for (int c=0;c<4;c++)
        wmma::store_matrix_sync(&Cs[(wm*32+r*16)*132 + wn*64+c*16], cf[r][c], 132,
                                wmma::mem_row_major);
    __syncthreads();
    #pragma unroll 4
    for (int i=0;i<64;i++){
      int idx=i*256+tid, tok=idx>>7, n=idx&127;
      int kh = n0+n;
      dst[((size_t)bm*Ln + l0+tok)*256 + kh] =
        __float2half_rn(Cs[tok*132+n] + bias[m*256+kh]);
    }
    __syncthreads();
  }
}

// ---------------- K2: bmm1 split-K, wmma, 2-stage cp.async, fp16 partials ----------------
__global__ void __launch_bounds__(256) k_gemm1w(){
  __shared__ char g1sm[43008];   // stages: As 2x2304h (9216B) | Bs2 2x8448h (33792B); Csf union
  __half* As0 = (__half*)g1sm;
  __half* As1 = (__half*)(g1sm + 4608);
  __half* Bs0 = (__half*)(g1sm + 9216);
  __half* Bs1 = (__half*)(g1sm + 26112);
  float*  Csf = (float*)g1sm;    // 64 x 132 (33792 B)
  __half* Asv[2] = {As0, As1};
  __half* Bsv[2] = {Bs0, Bs1};
  const int bm = blockIdx.x, sp = blockIdx.y;
  const int b = bm>>3, m = bm&7;
  const int tid = threadIdx.x, wid = tid>>5;
  const int wm = wid&1, wn = wid>>1;

  auto load_stage = [&](int st, int lb){
    { int r=tid>>3, u=tid&7;
      cpa16(&Asv[st][r*72+u*8], &g_xh[(size_t)(b*Ln+lb+r)*Dn + m*64 + u*8]); }
    #pragma unroll
    for (int i=0;i<4;i++){ int idx=i*256+tid, r=idx>>5, u=idx&31;
      cpa16(&Bsv[st][r*264+u*8], &g_W1h[((size_t)bm*Ln+lb+r)*256 + u*8]); }
    CPA_COMMIT();
  };

  wmma::fragment<wmma::accumulator,16,16,16,float> cf[2][4];
  #pragma unroll
  for (int r=0;r<2;r++)
    #pragma unroll
    for (int c=0;c<4;c++) wmma::fill_fragment(cf[r][c], 0.0f);

  const int lbase = sp*256;
  load_stage(0, lbase);
  for (int ck=0; ck<8; ck++){
    if (ck+1 < 8) { load_stage((ck+1)&1, lbase + (ck+1)*32); CPA_WAIT1(); }
    else          { CPA_WAIT0(); }
    __syncthreads();
    const __half* Ac = Asv[ck&1];
    const __half* Bc = Bsv[ck&1];
    #pragma unroll
    for (int ks=0; ks<32; ks+=16){
      wmma::fragment<wmma::matrix_a,16,16,16,__half,wmma::col_major> af[2];
      wmma::fragment<wmma::matrix_b,16,16,16,__half,wmma::row_major> bf[4];
      #pragma unroll
      for (int r=0;r<2;r++)
        wmma::load_matrix_sync(af[r], &Ac[ks*72 + wm*32 + r*16], 72);
      #pragma unroll
      for (int c=0;c<4;c++)
        wmma::load_matrix_sync(bf[c], &Bc[ks*264 + wn*64 + c*16], 264);
      #pragma unroll
      for (int r=0;r<2;r++)
        #pragma unroll
        for (int c=0;c<4;c++)
          wmma::mma_sync(cf[r][c], af[r], bf[c], cf[r][c]);
    }
    __syncthreads();
  }
  // epilogue: two N-half passes through fp32 smem stage, store fp16 partials
  #pragma unroll
  for (int p=0;p<2;p++){
    __syncthreads();
    if ((wn>>1) == p){
      int lc = (wn&1)*64;
      #pragma unroll
      for (int r=0;r<2;r++)
        #pragma unroll
        for (int c=0;c<4;c++)
          wmma::store_matrix_sync(&Csf[(wm*32+r*16)*132 + lc + c*16], cf[r][c],
                                  132, wmma::mem_row_major);
    }
    __syncthreads();
    #pragma unroll
    for (int i=0;i<4;i++){
      int idx = i*256 + tid;
      int d = idx>>4, u = idx&15;
      const float* src = &Csf[d*132 + u*8];
      __half tmp[8];
      #pragma unroll
      for (int j=0;j<8;j++) tmp[j] = __float2half_rn(src[j]);
      *(uint4*)&g_parth[((size_t)(bm*8+sp)*64 + d)*256 + p*128 + u*8] = *(uint4*)tmp;
    }
  }
}

// ---------------- K2b: reduce + gelu -> fp16 [bm][k][d] ----------------
__global__ void k_red1(){
  int g = blockIdx.x*256 + threadIdx.x;
  int bm = g>>14, r = g&16383;
  int k = r&255, d = r>>8;
  float s = 0.f;
  #pragma unroll
  for (int sp=0;sp<8;sp++)
    s += __half2float(g_parth[(size_t)((bm*8+sp)*64 + d)*KHn + k]);
  g_out1h[(size_t)bm*16384 + k*64 + d] = __float2half_rn(gelu_f(s));
}

// ---------------- K3: bmm2, wmma. M=128 l, N=64 d, K=256 kh ----------------
__global__ void __launch_bounds__(256) k_gemm2w(){
  __shared__ char s2[34816];
  __half* A2 = (__half*)s2;          // 128 x 72
  __half* B2 = (__half*)(s2+18432);  // 64 x 72
  float*  C2 = (float*)s2;           // 128 x 68 (union)
  const int l0 = blockIdx.x*128, bm = blockIdx.y;
  const int b = bm>>3, m = bm&7;
  const int tid = threadIdx.x, wid = tid>>5;
  const int wm = wid&3, wn = wid>>2;
  wmma::fragment<wmma::accumulator,16,16,16,float> cf[2][2];
  #pragma unroll
  for (int r=0;r<2;r++)
    #pragma unroll
    for (int c=0;c<2;c++) wmma::fill_fragment(cf[r][c], 0.0f);
  for (int kc=0; kc<256; kc+=64){
    #pragma unroll
    for (int i=0;i<4;i++){ int idx=i*256+tid, row=idx>>3, u=idx&7;
      *(uint4*)&A2[row*72+u*8] =
        *(const uint4*)&g_W2h[((size_t)bm*Ln+l0+row)*256 + kc + u*8]; }
    #pragma unroll
    for (int i=0;i<2;i++){ int idx=i*256+tid, row=idx>>3, u=idx&7;
      *(uint4*)&B2[row*72+u*8] =
        *(const uint4*)&g_out1h[(size_t)bm*16384 + (kc+row)*64 + u*8]; }
    __syncthreads();
    #pragma unroll
    for (int ks=0; ks<64; ks+=16){
      wmma::fragment<wmma::matrix_a,16,16,16,__half,wmma::row_major> af[2];
      wmma::fragment<wmma::matrix_b,16,16,16,__half,wmma::row_major> bf[2];
      #pragma unroll
      for (int r=0;r<2;r++)
        wmma::load_matrix_sync(af[r], &A2[(wm*32+r*16)*72 + ks], 72);
      #pragma unroll
      for (int c=0;c<2;c++)
        wmma::load_matrix_sync(bf[c], &B2[ks*72 + wn*32 + c*16], 72);
      #pragma unroll
      for (int r=0;r<2;r++)
        #pragma unroll
        for (int c=0;c<2;c++)
          wmma::mma_sync(cf[r][c], af[r], bf[c], cf[r][c]);
    }
    __syncthreads();
  }
  #pragma unroll
  for (int r=0;r<2;r++)
    #pragma unroll
    for (int c=0;c<2;c++)
      wmma::store_matrix_sync(&C2[(wm*32+r*16)*68 + wn*32+c*16], cf[r][c], 68,
                              wmma::mem_row_major);
  __syncthreads();
  #pragma unroll
  for (int i=0;i<8;i++){
    int idx=i*256+tid, row=idx>>4, q=idx&15;
    *(float4*)&g_mixpre[(size_t)(b*Ln+l0+row)*Dn + m*64 + q*4] =
      *(const float4*)&C2[row*68 + q*4];
  }
}

// ---------------- block reduce (128 thr) ----------------
__device__ __forceinline__ float blkSum128(float v){
  __shared__ float red[4];
  #pragma unroll
  for (int o=16;o>0;o>>=1) v += __shfl_down_sync(0xffffffffu, v, o);
  if ((threadIdx.x & 31) == 0) red[threadIdx.x>>5] = v;
  __syncthreads();
  float s = red[0]+red[1]+red[2]+red[3];
  __syncthreads();
  return s;
}

// ---------------- K4: mix = LN(mixpre); ln1h = fp16(LN(mix)) ----------------
__global__ void __launch_bounds__(128) k_lnmix(
    const float* __restrict__ gm, const float* __restrict__ bb0,
    const float* __restrict__ g1, const float* __restrict__ b1){
  const int t = blockIdx.x, tid = threadIdx.x;
  float v[4];
  #pragma unroll
  for (int i=0;i<4;i++) v[i] = g_mixpre[(size_t)t*Dn + tid + i*128];
  float mean = blkSum128(v[0]+v[1]+v[2]+v[3]) * (1.f/512.f);
  float q = 0.f;
  #pragma unroll
  for (int i=0;i<4;i++){ float d=v[i]-mean; q += d*d; }
  float inv = rsqrtf(blkSum128(q)*(1.f/512.f) + 1e-5f);
  float mv[4];
  #pragma unroll
  for (int i=0;i<4;i++){
    int c = tid + i*128;
    mv[i] = (v[i]-mean)*inv*gm[c] + bb0[c];
    g_mix[(size_t)t*Dn + c] = mv[i];
  }
  float mean2 = blkSum128(mv[0]+mv[1]+mv[2]+mv[3]) * (1.f/512.f);
  float q2 = 0.f;
  #pragma unroll
  for (int i=0;i<4;i++){ float d=mv[i]-mean2; q2 += d*d; }
  float inv2 = rsqrtf(blkSum128(q2)*(1.f/512.f) + 1e-5f);
  #pragma unroll
  for (int i=0;i<4;i++){
    int c = tid + i*128;
    g_ln1h[(size_t)t*Dn + c] = __float2half_rn((mv[i]-mean2)*inv2*g1[c] + b1[c]);
  }
}

// ---------------- K5/K8: wmma fp16 GEMM, 2-stage cp.async, K-chunk 64 ----------------
#define HG_SMEM 73728

__global__ void __launch_bounds__(256) k_hgemm(int mode,
    const float* __restrict__ bias, float* __restrict__ extout){
  extern __shared__ char wsmraw[];
  __half* Ast[2] = {(__half*)wsmraw,           (__half*)(wsmraw + 18432)};
  __half* Bst[2] = {(__half*)(wsmraw + 36864), (__half*)(wsmraw + 55296)};
  float*  Cs  = (float*)wsmraw;                 // 128 x 132
  const int tid = threadIdx.x, wid = tid>>5;
  const int wm = wid & 3, wn = wid >> 2;
  const int t0 = blockIdx.x*128;
  const int e0 = blockIdx.y * (mode ? 128 : 64);
  const __half* Xh = mode ? g_acth : g_ln1h;
  const __half* Wh = mode ? g_lwh  : g_bwh;

  auto load_stage = [&](int st, int kc){
    #pragma unroll
    for (int i=0;i<4;i++){ int idx=i*256+tid, r=idx>>3, u=idx&7;
      cpa16(&Ast[st][r*72 + u*8], &Xh[(size_t)(t0+r)*512 + kc + u*8]); }
    #pragma unroll
    for (int i=0;i<4;i++){ int idx=i*256+tid, r=idx>>3, u=idx&7;
      int er = mode ? (e0 + r) : ((r < 64) ? (e0 + r) : (512 + e0 + (r - 64)));
      cpa16(&Bst[st][r*72 + u*8], &Wh[(size_t)er*512 + kc + u*8]); }
    CPA_COMMIT();
  };

  wmma::fragment<wmma::accumulator,16,16,16,float> cf[2][4];
  #pragma unroll
  for (int r=0;r<2;r++)
    #pragma unroll
    for (int c=0;c<4;c++) wmma::fill_fragment(cf[r][c], 0.0f);

  load_stage(0, 0);
  for (int ck = 0; ck < 8; ck++) {
    if (ck+1 < 8) { load_stage((ck+1)&1, (ck+1)*64); CPA_WAIT1(); }
    else          { CPA_WAIT0(); }
    __syncthreads();
    const __half* Ac = Ast[ck&1];
    const __half* Bc = Bst[ck&1];
    #pragma unroll
    for (int ks = 0; ks < 64; ks += 16) {
      wmma::fragment<wmma::matrix_a,16,16,16,__half,wmma::row_major> af[2];
      wmma::fragment<wmma::matrix_b,16,16,16,__half,wmma::col_major> bf[4];
      wmma::load_matrix_sync(af[0], &Ac[(wm*32    )*72 + ks], 72);
      wmma::load_matrix_sync(af[1], &Ac[(wm*32 + 16)*72 + ks], 72);
      #pragma unroll
      for (int c=0;c<4;c++)
        wmma::load_matrix_sync(bf[c], &Bc[(wn*64 + c*16)*72 + ks], 72);
      #pragma unroll
      for (int r=0;r<2;r++)
        #pragma unroll
        for (int c=0;c<4;c++)
          wmma::mma_sync(cf[r][c], af[r], bf[c], cf[r][c]);
    }
    __syncthreads();
  }
  #pragma unroll
  for (int r=0;r<2;r++)
    #pragma unroll
    for (int c=0;c<4;c++)
      wmma::store_matrix_sync(&Cs[(wm*32 + r*16)*132 + wn*64 + c*16], cf[r][c],
                              132, wmma::mem_row_major);
  __syncthreads();

  if (mode == 0) {
    #pragma unroll
    for (int i=0;i<8;i++){
      int idx = i*256 + tid;
      int row = idx >> 4, jq = idx & 15;
      int j = jq*4;
      float4 ya = *(const float4*)&Cs[row*132 + j];
      float4 yb = *(const float4*)&Cs[row*132 + 64 + j];
      float4 ba = *(const float4*)&bias[e0 + j];
      float4 bbv= *(const float4*)&bias[512 + e0 + j];
      float ox = (ya.x + ba.x) * (1.f/(1.f+expf(-(yb.x+bbv.x))));
      float oy = (ya.y + ba.y) * (1.f/(1.f+expf(-(yb.y+bbv.y))));
      float oz = (ya.z + ba.z) * (1.f/(1.f+expf(-(yb.z+bbv.z))));
      float ow = (ya.w + ba.w) * (1.f/(1.f+expf(-(yb.w+bbv.w))));
      __half2* p = (__half2*)&g_gluh[(size_t)(t0+row)*512 + e0 + j];
      p[0] = __floats2half2_rn(ox, oy);
      p[1] = __floats2half2_rn(oz, ow);
    }
  } else {
    #pragma unroll
    for (int i=0;i<16;i++){
      int idx = i*256 + tid;
      int row = idx >> 5, jq = idx & 31;
      int j = jq*4;
      size_t o = (size_t)(t0+row)*512 + e0 + j;
      float4 cv = *(const float4*)&Cs[row*132 + j];
      float4 mv = *(const float4*)&g_mix[o];
      float4 lb4= *(const float4*)&bias[e0 + j];
      float4 ov;
      ov.x = mv.x + cv.x + lb4.x;
      ov.y = mv.y + cv.y + lb4.y;
      ov.z = mv.z + cv.z + lb4.z;
      ov.w = mv.w + cv.w + lb4.w;
      *(float4*)&extout[o] = ov;
    }
  }
}

// ---------------- K6: fused depthwise conv + LN2 + gelu -> acth (half2 channel pairs) ----------------
#define DW_SMEM 130304
__global__ void __launch_bounds__(256) k_dwln(
    const float* __restrict__ dww, const float* __restrict__ dwb,
    const float* __restrict__ g2, const float* __restrict__ b2){
  extern __shared__ char dsm[];
  __half* gsh  = (__half*)dsm;                 // 62 x 512
  float*  dw_s = (float*)(dsm + 63488);        // 32 x 512
  float*  red  = (float*)(dsm + 129024);       // 32 x 8
  float*  ms   = (float*)(dsm + 130048);       // 32
  float*  is   = ms + 32;                      // 32
  const int l0 = blockIdx.x*32, b = blockIdx.y;
  const int tid = threadIdx.x;

  #pragma unroll
  for (int i=0;i<16;i++){
    int idx=i*256+tid;
    if (idx < 3968){
      int row = idx>>6, u = idx&63;
      int l = l0-15+row;
      uint4 v = make_uint4(0u,0u,0u,0u);
      if (l>=0 && l<Ln) v = *(const uint4*)&g_gluh[((size_t)(b*Ln+l))*512 + u*8];
      *(uint4*)&gsh[row*512+u*8] = v;
    }
  }
  __syncthreads();
  {
    const int c2 = tid*2;   // channel pair
    float2 w[31];
    #pragma unroll
    for (int j=0;j<31;j++){
      w[j].x = dww[c2*31 + j];
      w[j].y = dww[(c2+1)*31 + j];
    }
    float bx = dwb[c2], by = dwb[c2+1];
    for (int tok=0; tok<32; tok++){
      float ax = bx, ay = by;
      const __half2* src = (const __half2*)&gsh[tok*512 + c2];
      #pragma unroll
      for (int j=0;j<31;j++){
        float2 v = __half22float2(src[j*256]);
        ax += v.x * w[j].x;
        ay += v.y * w[j].y;
      }
      dw_s[tok*512 + c2]     = ax;
      dw_s[tok*512 + c2 + 1] = ay;
    }
  }
  __syncthreads();
  const int tok = tid>>3, g = tid&7;
  float s=0.f;
  #pragma unroll 8
  for (int i=0;i<64;i++) s += dw_s[tok*512 + g + i*8];
  red[tok*8+g] = s;
  __syncthreads();
  float mean=0.f;
  #pragma unroll
  for (int k=0;k<8;k++) mean += red[tok*8+k];
  mean *= (1.f/512.f);
  __syncthreads();
  float q=0.f;
  #pragma unroll 8
  for (int i=0;i<64;i++){ float d = dw_s[tok*512 + g + i*8] - mean; q += d*d; }
  red[tok*8+g] = q;
  __syncthreads();
  float var=0.f;
  #pragma unroll
  for (int k=0;k<8;k++) var += red[tok*8+k];
  float inv = rsqrtf(var*(1.f/512.f) + 1e-5f);
  if (g==0){ ms[tok]=mean; is[tok]=inv; }
  __syncthreads();
  for (int i=0;i<64;i++){
    int idx = i*256 + tid;
    int t2 = idx>>9, c = idx&511;
    float v = (dw_s[idx]-ms[t2])*is[t2]*g2[c] + b2[c];
    g_acth[((size_t)(b*Ln + l0+t2))*512 + c] = __float2half_rn(gelu_f(v));
  }
}

// ---------------- launch ----------------
extern "C" void kernel_launch(void* const* d_in, const int* in_sizes, int n_in,
                              void* d_out, int out_size) {
  const float* x      = (const float*)d_in[0];
  const float* w1f1w  = (const float*)d_in[1];
  const float* w1f1b  = (const float*)d_in[2];
  const float* w1f2w  = (const float*)d_in[3];
  const float* w1f2b  = (const float*)d_in[4];
  const float* w2f1w  = (const float*)d_in[5];
  const float* w2f1b  = (const float*)d_in[6];
  const float* w2f2w  = (const float*)d_in[7];
  const float* w2f2b  = (const float*)d_in[8];
  const float* lnmg   = (const float*)d_in[9];
  const float* lnmb   = (const float*)d_in[10];
  const float* ln1g   = (const float*)d_in[11];
  const float* ln1b   = (const float*)d_in[12];
  const float* bw     = (const float*)d_in[13];
  const float* bb     = (const float*)d_in[14];
  const float* dww    = (const float*)d_in[15];
  const float* dwb    = (const float*)d_in[16];
  const float* ln2g   = (const float*)d_in[17];
  const float* ln2b   = (const float*)d_in[18];
  const float* lw     = (const float*)d_in[19];
  const float* lb     = (const float*)d_in[20];
  float* out = (float*)d_out;

  cudaFuncSetAttribute(k_pmlpA, cudaFuncAttributeMaxDynamicSharedMemorySize, PA_SMEM);
  cudaFuncSetAttribute(k_pmlpB, cudaFuncAttributeMaxDynamicSharedMemorySize, PA_SMEM);
  cudaFuncSetAttribute(k_hgemm, cudaFuncAttributeMaxDynamicSharedMemorySize, HG_SMEM);
  cudaFuncSetAttribute(k_dwln,  cudaFuncAttributeMaxDynamicSharedMemorySize, DW_SMEM);

  k_prep<<<41216, 256>>>(x, w1f1w, w2f1w, w1f2w, w2f2w, bw, lw);
  k_pmlpA<<<dim3(16, 64), 256, PA_SMEM>>>(x, w1f1b, w2f1b);
  k_pmlpB<<<dim3(16, 128), 256, PA_SMEM>>>(w1f2b, w2f2b);
  k_gemm1w<<<dim3(BMn, 8), 256>>>();
  k_red1<<<4096, 256>>>();
  k_gemm2w<<<dim3(16, BMn), 256>>>();
  k_lnmix<<<Tn, 128>>>(lnmg, lnmb, ln1g, ln1b);
  k_hgemm<<<dim3(Tn/128, 8), 256, HG_SMEM>>>(0, bb, nullptr);
  k_dwln<<<dim3(Ln/32, Bn), 256, DW_SMEM>>>(dww, dwb, ln2g, ln2b);
  k_hgemm<<<dim3(Tn/128, 4), 256, HG_SMEM>>>(1, lb, out);
}